// round 7
// baseline (speedup 1.0000x reference)
#include <cuda_runtime.h>
#include <cstdint>
#include <math.h>

// CropAndResize: x [B,H,W,C=4] fp32, boxes [B,4] (y1,x1,y2,x2 in [0,1]),
// output [B,crop,crop,4] fp32 bilinear.
//
// R1 structure (1 px/thread, 4 corner gathers, minimal DRAM bytes) but the
// gathers go through cp.async.cg (LDGSTS, 16B) into smem. LDGSTS has no
// observed outstanding-depth cap on sm_103a, unlike the LDG path whose
// SM-wide in-flight line tracking (~64 lines) was capping DRAM bandwidth
// at ~3.2 TB/s in rounds 1-3.

#define TPB 256

__device__ __forceinline__ void cp_async16(uint32_t smem_addr, const void* gptr) {
    asm volatile("cp.async.cg.shared.global [%0], [%1], 16;\n"
                 :: "r"(smem_addr), "l"(gptr));
}

__global__ __launch_bounds__(TPB)
void crop_resize_cpasync_kernel(const float* __restrict__ x,
                                const float* __restrict__ boxes,
                                float* __restrict__ out,
                                int H, int W, int crop) {
    // [corner][thread] layout -> readback LDS.128 is conflict-free
    __shared__ float4 corners[4][TPB];

    const int b   = blockIdx.y;
    const int idx = blockIdx.x * TPB + threadIdx.x;
    const int npx = crop * crop;
    const int tid = threadIdx.x;

    const float y1 = __ldg(&boxes[b * 4 + 0]);
    const float x1 = __ldg(&boxes[b * 4 + 1]);
    const float y2 = __ldg(&boxes[b * 4 + 2]);
    const float x2 = __ldg(&boxes[b * 4 + 3]);

    const float inv = 1.0f / (float)(crop - 1);
    const float hm1 = (float)(H - 1);
    const float wm1 = (float)(W - 1);

    const bool live = (idx < npx);
    const int id  = live ? idx : 0;
    const int row = id / crop;
    const int col = id - row * crop;

    const float in_y = (y1 + (float)row * inv * (y2 - y1)) * hm1;
    const float in_x = (x1 + (float)col * inv * (x2 - x1)) * wm1;

    const bool valid = live &&
                       (in_y >= 0.0f) && (in_y <= hm1) &&
                       (in_x >= 0.0f) && (in_x <= wm1);

    const float top_f  = floorf(in_y);
    const float left_f = floorf(in_x);
    const float yl = in_y - top_f;
    const float xl = in_x - left_f;

    int t = min(max((int)top_f, 0), H - 1);
    int bo = min(t + 1, H - 1);
    int l = min(max((int)left_f, 0), W - 1);
    int r = min(l + 1, W - 1);

    const float4* __restrict__ xb = (const float4*)(x) + (size_t)b * H * W;
    const size_t o_tl = (size_t)t  * W + l;
    const size_t o_tr = (size_t)t  * W + r;
    const size_t o_bl = (size_t)bo * W + l;
    const size_t o_br = (size_t)bo * W + r;

    // Issue 4 deep-pipeline async copies (16B each), then drain.
    const uint32_t s0 = (uint32_t)__cvta_generic_to_shared(&corners[0][tid]);
    const uint32_t s1 = (uint32_t)__cvta_generic_to_shared(&corners[1][tid]);
    const uint32_t s2 = (uint32_t)__cvta_generic_to_shared(&corners[2][tid]);
    const uint32_t s3 = (uint32_t)__cvta_generic_to_shared(&corners[3][tid]);

    cp_async16(s0, (const void*)(xb + o_tl));
    cp_async16(s1, (const void*)(xb + o_tr));
    cp_async16(s2, (const void*)(xb + o_bl));
    cp_async16(s3, (const void*)(xb + o_br));
    asm volatile("cp.async.commit_group;\n" ::: "memory");
    asm volatile("cp.async.wait_group 0;\n" ::: "memory");

    if (!live) return;

    float4 res = make_float4(0.f, 0.f, 0.f, 0.f);
    if (valid) {
        const float4 tl4 = corners[0][tid];
        const float4 tr4 = corners[1][tid];
        const float4 bl4 = corners[2][tid];
        const float4 br4 = corners[3][tid];

        const float tx0 = fmaf(tr4.x - tl4.x, xl, tl4.x);
        const float ty0 = fmaf(tr4.y - tl4.y, xl, tl4.y);
        const float tz0 = fmaf(tr4.z - tl4.z, xl, tl4.z);
        const float tw0 = fmaf(tr4.w - tl4.w, xl, tl4.w);
        const float bx0 = fmaf(br4.x - bl4.x, xl, bl4.x);
        const float by0 = fmaf(br4.y - bl4.y, xl, bl4.y);
        const float bz0 = fmaf(br4.z - bl4.z, xl, bl4.z);
        const float bw0 = fmaf(br4.w - bl4.w, xl, bl4.w);
        res.x = fmaf(bx0 - tx0, yl, tx0);
        res.y = fmaf(by0 - ty0, yl, ty0);
        res.z = fmaf(bz0 - tz0, yl, tz0);
        res.w = fmaf(bw0 - tw0, yl, tw0);
    }

    float4* __restrict__ outb = (float4*)(out) + (size_t)b * npx;
    outb[idx] = res;
}

extern "C" void kernel_launch(void* const* d_in, const int* in_sizes, int n_in,
                              void* d_out, int out_size) {
    const float* x     = (const float*)d_in[0];
    const float* boxes = (const float*)d_in[1];
    float* out = (float*)d_out;

    const int B = in_sizes[1] / 4;          // boxes is [B,4]
    const int C = 4;
    const long long hw = (long long)in_sizes[0] / ((long long)B * C);
    int H = (int)(sqrt((double)hw) + 0.5);
    int W = H;
    const long long cc = (long long)out_size / ((long long)B * C);
    int crop = (int)(sqrt((double)cc) + 0.5);

    const int npx = crop * crop;
    dim3 grid((npx + TPB - 1) / TPB, B);
    crop_resize_cpasync_kernel<<<grid, TPB>>>(x, boxes, out, H, W, crop);
}

// round 8
// speedup vs baseline: 1.1000x; 1.1000x over previous
#include <cuda_runtime.h>
#include <cstdint>
#include <math.h>

// CropAndResize: x [B,H,W,C=4] fp32, boxes [B,4] (y1,x1,y2,x2 in [0,1]),
// output [B,crop,crop,4] fp32 bilinear.
//
// Lane-pair cooperative gather: 2 lanes per output pixel. tl|tr form one
// contiguous 32B span; even lane loads the left float4, odd lane the right
// float4 -> ONE LDG.128 per source row per warp (16 px) instead of two,
// halving the dominant L1tex gather wavefronts. Each lane v-lerps its
// column, a single shfl_down(1) delivers the right column to the even
// lane, which h-lerps and stores (16 contiguous float4 -> 2 wavefronts).
//
// Index form: t in [0,H-2], l in [0,W-2], yl = in_y - t, xl = in_x - l.
// Identical results to the reference clamping (at in_y == H-1 the lerp
// weight is 1.0 and selects row H-1), and +1 / +W stay in bounds.

#define TPB 256   // 8 warps/block, 1 warp = 16 output pixels of one row

__global__ __launch_bounds__(TPB)
void crop_resize_pair_kernel(const float* __restrict__ x,
                             const float* __restrict__ boxes,
                             float* __restrict__ out,
                             int H, int W, int crop, int chunks, int nwarps) {
    const int wid  = threadIdx.x >> 5;
    const int lane = threadIdx.x & 31;
    const int gw   = blockIdx.x * (TPB / 32) + wid;
    if (gw >= nwarps) return;                  // warp-uniform

    const int per_b = crop * chunks;
    const int b     = gw / per_b;
    const int rem   = gw - b * per_b;
    const int r     = rem / chunks;            // output row
    const int chunk = rem - r * chunks;
    const int c     = (chunk << 4) + (lane >> 1);   // output col of this pair
    const bool live = (c < crop);
    const int c_eff = live ? c : (crop - 1);

    const float4 bx = __ldg((const float4*)boxes + b);  // y1,x1,y2,x2
    const float inv = 1.0f / (float)(crop - 1);
    const float hm1 = (float)(H - 1);
    const float wm1 = (float)(W - 1);

    const float in_y = (bx.x + (float)r     * inv * (bx.z - bx.x)) * hm1;
    const float in_x = (bx.y + (float)c_eff * inv * (bx.w - bx.y)) * wm1;

    const bool valid = live &&
                       (in_y >= 0.0f) && (in_y <= hm1) &&
                       (in_x >= 0.0f) && (in_x <= wm1);

    // clamped corner indices; truncation == floor for the valid (>=0) range,
    // out-of-range values are clamped and masked to zero below.
    const int t = min(max((int)in_y, 0), H - 2);
    const int l = min(max((int)in_x, 0), W - 2);
    const float yl = in_y - (float)t;
    const float xl = in_x - (float)l;

    const float4* __restrict__ xb = (const float4*)(x) + (size_t)b * H * W;
    const size_t base = (size_t)t * W + l + (lane & 1);  // even: left col, odd: right col

    const float4 ct = __ldg(xb + base);        // top corner of this lane's column
    const float4 cb = __ldg(xb + base + W);    // bottom corner

    // vertical lerp (per lane, own column)
    float4 v;
    v.x = fmaf(cb.x - ct.x, yl, ct.x);
    v.y = fmaf(cb.y - ct.y, yl, ct.y);
    v.z = fmaf(cb.z - ct.z, yl, ct.z);
    v.w = fmaf(cb.w - ct.w, yl, ct.w);

    // even lane fetches odd lane's (right column) result
    float4 vr;
    vr.x = __shfl_down_sync(0xffffffffu, v.x, 1);
    vr.y = __shfl_down_sync(0xffffffffu, v.y, 1);
    vr.z = __shfl_down_sync(0xffffffffu, v.z, 1);
    vr.w = __shfl_down_sync(0xffffffffu, v.w, 1);

    if ((lane & 1) == 0 && live) {
        float4 res = make_float4(0.f, 0.f, 0.f, 0.f);
        if (valid) {
            res.x = fmaf(vr.x - v.x, xl, v.x);
            res.y = fmaf(vr.y - v.y, xl, v.y);
            res.z = fmaf(vr.z - v.z, xl, v.z);
            res.w = fmaf(vr.w - v.w, xl, v.w);
        }
        float4* __restrict__ outrow =
            (float4*)(out) + ((size_t)b * crop + r) * crop;
        outrow[c] = res;
    }
}

extern "C" void kernel_launch(void* const* d_in, const int* in_sizes, int n_in,
                              void* d_out, int out_size) {
    const float* x     = (const float*)d_in[0];
    const float* boxes = (const float*)d_in[1];
    float* out = (float*)d_out;

    const int B = in_sizes[1] / 4;          // boxes is [B,4]
    const int C = 4;
    const long long hw = (long long)in_sizes[0] / ((long long)B * C);
    int H = (int)(sqrt((double)hw) + 0.5);
    int W = H;
    const long long cc = (long long)out_size / ((long long)B * C);
    int crop = (int)(sqrt((double)cc) + 0.5);

    const int chunks = (crop + 15) / 16;    // 16 px per warp
    const int nwarps = B * crop * chunks;
    const int wpb    = TPB / 32;
    const int blocks = (nwarps + wpb - 1) / wpb;
    crop_resize_pair_kernel<<<blocks, TPB>>>(x, boxes, out, H, W, crop,
                                             chunks, nwarps);
}

// round 9
// speedup vs baseline: 1.7983x; 1.6348x over previous
#include <cuda_runtime.h>
#include <cstdint>
#include <math.h>

// CropAndResize: x [B,H,W,C=4] fp32, boxes [B,4] (y1,x1,y2,x2 in [0,1]),
// output [B,crop,crop,4] fp32 bilinear.
//
// R1's minimal-byte direct-gather structure with the scalar overhead
// stripped out:
//  - grid = (crop, B): row/batch from blockIdx -> no div/mod, and all
//    row-dependent math (in_y, t, yl, base pointers) is blockIdx-uniform,
//    so ptxas moves it to the uniform datapath (off the per-lane issue slots).
//  - col = threadIdx.x (+ chunk loop for generality); exact fit at crop%32==0.
//  - box loaded as one float4.
//  - clamp form t in [0,H-2], yl = in_y - t (validated vs reference in R8).

__global__ __launch_bounds__(256)
void crop_resize_row2d_kernel(const float* __restrict__ x,
                              const float* __restrict__ boxes,
                              float* __restrict__ out,
                              int H, int W, int crop) {
    const int r = blockIdx.x;   // output row   (uniform)
    const int b = blockIdx.y;   // batch        (uniform)

    const float4 bx = __ldg((const float4*)boxes + b);   // y1,x1,y2,x2
    const float inv = 1.0f / (float)(crop - 1);
    const float hm1 = (float)(H - 1);
    const float wm1 = (float)(W - 1);

    // ---- row-uniform vertical math (uniform pipe) ----
    const float in_y = (bx.x + (float)r * inv * (bx.z - bx.x)) * hm1;
    const bool valid_y = (in_y >= 0.0f) && (in_y <= hm1);
    const int t = min(max((int)in_y, 0), H - 2);
    const float yl = in_y - (float)t;

    const float4* __restrict__ rowT = (const float4*)(x) + ((size_t)b * H + t) * W;
    float4* __restrict__ outrow = (float4*)(out) + ((size_t)b * crop + r) * crop;

    const float xoff = bx.y * wm1;
    const float xscl = inv * (bx.w - bx.y) * wm1;

    for (int c = threadIdx.x; c < crop; c += blockDim.x) {
        const float in_x = fmaf((float)c, xscl, xoff);
        const bool valid = valid_y && (in_x >= 0.0f) && (in_x <= wm1);

        const int l = min(max((int)in_x, 0), W - 2);
        const float xl = in_x - (float)l;

        const float4 tl4 = __ldg(rowT + l);
        const float4 tr4 = __ldg(rowT + l + 1);
        const float4 bl4 = __ldg(rowT + l + W);
        const float4 br4 = __ldg(rowT + l + W + 1);

        float4 res = make_float4(0.f, 0.f, 0.f, 0.f);
        if (valid) {
            const float tx0 = fmaf(tr4.x - tl4.x, xl, tl4.x);
            const float ty0 = fmaf(tr4.y - tl4.y, xl, tl4.y);
            const float tz0 = fmaf(tr4.z - tl4.z, xl, tl4.z);
            const float tw0 = fmaf(tr4.w - tl4.w, xl, tl4.w);
            const float bx0 = fmaf(br4.x - bl4.x, xl, bl4.x);
            const float by0 = fmaf(br4.y - bl4.y, xl, bl4.y);
            const float bz0 = fmaf(br4.z - bl4.z, xl, bl4.z);
            const float bw0 = fmaf(br4.w - bl4.w, xl, bl4.w);
            res.x = fmaf(bx0 - tx0, yl, tx0);
            res.y = fmaf(by0 - ty0, yl, ty0);
            res.z = fmaf(bz0 - tz0, yl, tz0);
            res.w = fmaf(bw0 - tw0, yl, tw0);
        }
        outrow[c] = res;
    }
}

extern "C" void kernel_launch(void* const* d_in, const int* in_sizes, int n_in,
                              void* d_out, int out_size) {
    const float* x     = (const float*)d_in[0];
    const float* boxes = (const float*)d_in[1];
    float* out = (float*)d_out;

    const int B = in_sizes[1] / 4;          // boxes is [B,4]
    const int C = 4;
    const long long hw = (long long)in_sizes[0] / ((long long)B * C);
    int H = (int)(sqrt((double)hw) + 0.5);
    int W = H;
    const long long cc = (long long)out_size / ((long long)B * C);
    int crop = (int)(sqrt((double)cc) + 0.5);

    // One block per output row; threads cover the row (exact fit for 224).
    int tpb = ((crop + 31) / 32) * 32;
    if (tpb > 256) tpb = 256;               // chunk loop handles the rest
    dim3 grid(crop, B);
    crop_resize_row2d_kernel<<<grid, tpb>>>(x, boxes, out, H, W, crop);
}